// round 12
// baseline (speedup 1.0000x reference)
#include <cuda_runtime.h>

#define NN 100000
#define EE 1600000
#define D 64
#define BN_EPS 1e-5f
#define CAP 64                       // per-node neighbor capacity (Poisson(16) max ~40)
#define MAXOVER 8192                 // overflow side-list capacity
#define RPAD 66                      // padded row for gemm1 stat reduction

// Packed f32x2 FMA (Blackwell): d = a*b + c per 32-bit lane. PTX-only.
#define FMA_F32X2(d, a, b, c) \
    asm("fma.rn.f32x2 %0, %1, %2, %3;" : "=l"(d) : "l"(a), "l"(b), "l"(c))
#define PACK_F32X2(out, lo, hi) \
    asm("mov.b64 %0, {%1, %2};" : "=l"(out) : "f"(lo), "f"(hi))

// Scratch (device globals — no allocation allowed).
__device__ __align__(16) float g_h [NN * D];
__device__ __align__(16) float g_h1[NN * D];
__device__ __align__(16) float g_sum[D];
__device__ __align__(16) float g_sumsq[D];
__device__ __align__(16) int   g_cursor[NN];
__device__ __align__(16) int   g_col[NN * CAP];
__device__ __align__(16) int2  g_over[MAXOVER];
__device__            int      g_overn;

// ---------------------------------------------------------------------------
// 1: zero cursors + BN stat accumulators + overflow counter
// ---------------------------------------------------------------------------
__global__ void k_zero() {
    int i = blockIdx.x * blockDim.x + threadIdx.x;
    if (i < NN) g_cursor[i] = 0;
    if (i < D) { g_sum[i] = 0.f; g_sumsq[i] = 0.f; }
    if (i == D) g_overn = 0;
}

// ---------------------------------------------------------------------------
// 2: direct bucket scatter — no histogram, no scan. Edges whose bucket is
//    full (essentially never) go to the overflow side list.
// ---------------------------------------------------------------------------
__global__ void k_fill(const int* __restrict__ ei) {
    int e4 = blockIdx.x * blockDim.x + threadIdx.x;
    if (e4 >= EE / 4) return;
    int4 s = ((const int4*)ei)[e4];
    int4 d = ((const int4*)(ei + EE))[e4];
#pragma unroll
    for (int q = 0; q < 4; q++) {
        int src = (q == 0) ? s.x : (q == 1) ? s.y : (q == 2) ? s.z : s.w;
        int dst = (q == 0) ? d.x : (q == 1) ? d.y : (q == 2) ? d.z : d.w;
        int pos = atomicAdd(&g_cursor[dst], 1);
        if (pos < CAP) {
            g_col[dst * CAP + pos] = src;
        } else {
            int oi = atomicAdd(&g_overn, 1);
            if (oi < MAXOVER) g_over[oi] = make_int2(src, dst);
        }
    }
}

// ---------------------------------------------------------------------------
// 3: gather. One warp per node; lane owns a float2. 8-way edge unroll.
//    Overflow edges (normally none) are folded in before the store —
//    each node is owned by exactly one warp, so no atomics needed.
// ---------------------------------------------------------------------------
__global__ void __launch_bounds__(256) k_gather(const float* __restrict__ x,
                                                const float* __restrict__ eps_p) {
    const int w = (blockIdx.x * blockDim.x + threadIdx.x) >> 5;
    const int lane = threadIdx.x & 31;
    if (w >= NN) return;
    const int beg = w * CAP;
    const int end = beg + min(g_cursor[w], CAP);
    const float2* __restrict__ x2 = (const float2*)x;   // row = 32 float2

    float s0x = 0.f, s0y = 0.f, s1x = 0.f, s1y = 0.f;
    float s2x = 0.f, s2y = 0.f, s3x = 0.f, s3y = 0.f;
    int j = beg;
    for (; j + 7 < end; j += 8) {
        int c0 = g_col[j],     c1 = g_col[j + 1];
        int c2 = g_col[j + 2], c3 = g_col[j + 3];
        int c4 = g_col[j + 4], c5 = g_col[j + 5];
        int c6 = g_col[j + 6], c7 = g_col[j + 7];
        float2 v0 = x2[(size_t)c0 * 32 + lane];
        float2 v1 = x2[(size_t)c1 * 32 + lane];
        float2 v2 = x2[(size_t)c2 * 32 + lane];
        float2 v3 = x2[(size_t)c3 * 32 + lane];
        float2 v4 = x2[(size_t)c4 * 32 + lane];
        float2 v5 = x2[(size_t)c5 * 32 + lane];
        float2 v6 = x2[(size_t)c6 * 32 + lane];
        float2 v7 = x2[(size_t)c7 * 32 + lane];
        s0x += v0.x; s0y += v0.y;  s1x += v1.x; s1y += v1.y;
        s2x += v2.x; s2y += v2.y;  s3x += v3.x; s3y += v3.y;
        s0x += v4.x; s0y += v4.y;  s1x += v5.x; s1y += v5.y;
        s2x += v6.x; s2y += v6.y;  s3x += v7.x; s3y += v7.y;
    }
    for (; j < end; j++) {
        int c0 = g_col[j];
        float2 v0 = x2[(size_t)c0 * 32 + lane];
        s0x += v0.x; s0y += v0.y;
    }
    // overflow fold-in (normally g_overn == 0; one broadcast LDG per warp)
    const int novr = g_overn;
    if (novr > 0) {
        const int lim = novr < MAXOVER ? novr : MAXOVER;
        for (int e = 0; e < lim; e++) {
            int2 ed = g_over[e];
            if (ed.y == w) {
                float2 v = x2[(size_t)ed.x * 32 + lane];
                s0x += v.x; s0y += v.y;
            }
        }
    }
    const float sc = 1.f + *eps_p;
    float2 xv = x2[(size_t)w * 32 + lane];
    float2 o;
    o.x = sc * xv.x + ((s0x + s1x) + (s2x + s3x));
    o.y = sc * xv.y + ((s0y + s1y) + (s2y + s3y));
    ((float2*)g_h)[(size_t)w * 32 + lane] = o;
}

// ---------------------------------------------------------------------------
// 4: h1 = h @ W1 + b1 (FFMA2) + fused BN column stats (smem reduction).
// ---------------------------------------------------------------------------
__global__ void __launch_bounds__(128) k_gemm1(const float* __restrict__ W1,
                                               const float* __restrict__ b1) {
    __shared__ __align__(16) float pool[128 * RPAD];   // 33.8 KB, time-sliced
    float* Ws = pool;
    float* bs = pool + D * D;
    const int tid = threadIdx.x;
    for (int i = tid; i < D * D; i += blockDim.x) Ws[i] = W1[i];
    if (tid < D) bs[tid] = b1[tid];
    __syncthreads();

    const int row = blockIdx.x * blockDim.x + tid;
    const bool valid = row < NN;

    unsigned long long acc2[D / 2];
    if (valid) {
        const unsigned long long* bs2 = (const unsigned long long*)bs;
#pragma unroll
        for (int j = 0; j < D / 2; j++) acc2[j] = bs2[j];

        const float4* __restrict__ hr = (const float4*)(g_h + (size_t)row * D);
        for (int k4 = 0; k4 < D / 4; k4++) {
            float4 hv = hr[k4];
#pragma unroll
            for (int kk = 0; kk < 4; kk++) {
                const float hk = ((const float*)&hv)[kk];
                unsigned long long hk2;
                PACK_F32X2(hk2, hk, hk);
                const ulonglong2* wrow =
                    (const ulonglong2*)&Ws[(k4 * 4 + kk) * D];
#pragma unroll
                for (int j8 = 0; j8 < D / 8; j8++) {
                    ulonglong2 wv0 = wrow[j8 * 2];
                    ulonglong2 wv1 = wrow[j8 * 2 + 1];
                    FMA_F32X2(acc2[j8 * 4 + 0], hk2, wv0.x, acc2[j8 * 4 + 0]);
                    FMA_F32X2(acc2[j8 * 4 + 1], hk2, wv0.y, acc2[j8 * 4 + 1]);
                    FMA_F32X2(acc2[j8 * 4 + 2], hk2, wv1.x, acc2[j8 * 4 + 2]);
                    FMA_F32X2(acc2[j8 * 4 + 3], hk2, wv1.y, acc2[j8 * 4 + 3]);
                }
            }
        }
        ulonglong2* out = (ulonglong2*)(g_h1 + (size_t)row * D);
#pragma unroll
        for (int j4 = 0; j4 < D / 4; j4++) {
            ulonglong2 o;
            o.x = acc2[j4 * 2];
            o.y = acc2[j4 * 2 + 1];
            out[j4] = o;
        }
    } else {
#pragma unroll
        for (int j = 0; j < D / 2; j++) acc2[j] = 0ull;
    }

    // fused BN stats through the (now dead) smem pool
    __syncthreads();
    unsigned long long* red2 = (unsigned long long*)(pool + tid * RPAD);
#pragma unroll
    for (int j = 0; j < D / 2; j++) red2[j] = acc2[j];
    __syncthreads();
    if (tid < D) {
        float s = 0.f, q = 0.f;
        for (int i = 0; i < 128; i++) {
            float v = pool[i * RPAD + tid];
            s += v; q += v * v;
        }
        atomicAdd(&g_sum[tid], s);
        atomicAdd(&g_sumsq[tid], q);
    }
}

// ---------------------------------------------------------------------------
// 5: out = relu(BN(h1)) @ W2 + b2 — FFMA2, BN folded in.
// ---------------------------------------------------------------------------
__global__ void __launch_bounds__(128) k_gemm2(const float* __restrict__ W2,
                                               const float* __restrict__ b2,
                                               const float* __restrict__ gamma,
                                               const float* __restrict__ beta,
                                               float* __restrict__ out) {
    __shared__ __align__(16) float Ws[D * D];
    __shared__ __align__(16) float scl[D];
    __shared__ __align__(16) float sft[D];
    __shared__ __align__(16) float bs[D];
    const int tid = threadIdx.x;
    for (int i = tid; i < D * D; i += blockDim.x) Ws[i] = W2[i];
    if (tid < D) {
        const float inv_n = 1.f / (float)NN;
        float mean = g_sum[tid] * inv_n;
        float var  = g_sumsq[tid] * inv_n - mean * mean;
        float rstd = rsqrtf(var + BN_EPS);
        float s = rstd * gamma[tid];
        scl[tid] = s;
        sft[tid] = beta[tid] - mean * s;
        bs[tid]  = b2[tid];
    }
    __syncthreads();

    const int row = blockIdx.x * blockDim.x + tid;
    if (row >= NN) return;

    unsigned long long acc2[D / 2];
    const unsigned long long* bs2 = (const unsigned long long*)bs;
#pragma unroll
    for (int j = 0; j < D / 2; j++) acc2[j] = bs2[j];

    const float4* __restrict__ hr = (const float4*)(g_h1 + (size_t)row * D);
    for (int k4 = 0; k4 < D / 4; k4++) {
        float4 hv = hr[k4];
#pragma unroll
        for (int kk = 0; kk < 4; kk++) {
            const int k = k4 * 4 + kk;
            float hk = ((const float*)&hv)[kk];
            hk = fmaxf(hk * scl[k] + sft[k], 0.f);        // BN + ReLU
            unsigned long long hk2;
            PACK_F32X2(hk2, hk, hk);
            const ulonglong2* wrow = (const ulonglong2*)&Ws[k * D];
#pragma unroll
            for (int j8 = 0; j8 < D / 8; j8++) {
                ulonglong2 wv0 = wrow[j8 * 2];
                ulonglong2 wv1 = wrow[j8 * 2 + 1];
                FMA_F32X2(acc2[j8 * 4 + 0], hk2, wv0.x, acc2[j8 * 4 + 0]);
                FMA_F32X2(acc2[j8 * 4 + 1], hk2, wv0.y, acc2[j8 * 4 + 1]);
                FMA_F32X2(acc2[j8 * 4 + 2], hk2, wv1.x, acc2[j8 * 4 + 2]);
                FMA_F32X2(acc2[j8 * 4 + 3], hk2, wv1.y, acc2[j8 * 4 + 3]);
            }
        }
    }
    ulonglong2* o4 = (ulonglong2*)(out + (size_t)row * D);
#pragma unroll
    for (int j4 = 0; j4 < D / 4; j4++) {
        ulonglong2 o;
        o.x = acc2[j4 * 2];
        o.y = acc2[j4 * 2 + 1];
        o4[j4] = o;
    }
}

// ---------------------------------------------------------------------------
extern "C" void kernel_launch(void* const* d_in, const int* in_sizes, int n_in,
                              void* d_out, int out_size) {
    const float* x     = (const float*)d_in[0];
    const int*   ei    = (const int*)  d_in[1];   // int32 (JAX demotes int64)
    const float* eps   = (const float*)d_in[2];
    const float* W1    = (const float*)d_in[3];
    const float* b1    = (const float*)d_in[4];
    const float* gamma = (const float*)d_in[5];
    const float* beta  = (const float*)d_in[6];
    const float* W2    = (const float*)d_in[7];
    const float* b2    = (const float*)d_in[8];
    float* out = (float*)d_out;

    k_zero  <<<(NN + 255) / 256, 256>>>();
    k_fill  <<<(EE / 4 + 255) / 256, 256>>>(ei);
    k_gather<<<(NN * 32 + 255) / 256, 256>>>(x, eps);
    k_gemm1 <<<(NN + 127) / 128, 128>>>(W1, b1);
    k_gemm2 <<<(NN + 127) / 128, 128>>>(W2, b2, gamma, beta, out);
}

// round 13
// speedup vs baseline: 1.1153x; 1.1153x over previous
#include <cuda_runtime.h>

#define NN 100000
#define EE 1600000
#define D 64
#define BN_EPS 1e-5f
#define CAP 64                       // per-node neighbor capacity (Poisson(16) max ~40)
#define MAXOVER 8192                 // overflow side-list capacity
#define RPAD 66                      // padded smem row stride (floats)

// Packed f32x2 FMA (Blackwell): d = a*b + c per 32-bit lane. PTX-only.
#define FMA_F32X2(d, a, b, c) \
    asm("fma.rn.f32x2 %0, %1, %2, %3;" : "=l"(d) : "l"(a), "l"(b), "l"(c))
#define PACK_F32X2(out, lo, hi) \
    asm("mov.b64 %0, {%1, %2};" : "=l"(out) : "f"(lo), "f"(hi))

// Scratch (device globals — no allocation allowed).
__device__ __align__(16) float g_h [NN * D];
__device__ __align__(16) float g_h1[NN * D];
__device__ __align__(16) float g_sum[D];
__device__ __align__(16) float g_sumsq[D];
__device__ __align__(16) int   g_cursor[NN];
__device__ __align__(16) int   g_col[NN * CAP];
__device__ __align__(16) int2  g_over[MAXOVER];
__device__            int      g_overn;

// ---------------------------------------------------------------------------
// 1: zero cursors + BN stat accumulators + overflow counter
// ---------------------------------------------------------------------------
__global__ void k_zero() {
    int i = blockIdx.x * blockDim.x + threadIdx.x;
    if (i < NN) g_cursor[i] = 0;
    if (i < D) { g_sum[i] = 0.f; g_sumsq[i] = 0.f; }
    if (i == D) g_overn = 0;
}

// ---------------------------------------------------------------------------
// 2: direct bucket scatter — no histogram, no scan.
// ---------------------------------------------------------------------------
__global__ void k_fill(const int* __restrict__ ei) {
    int e4 = blockIdx.x * blockDim.x + threadIdx.x;
    if (e4 >= EE / 4) return;
    int4 s = ((const int4*)ei)[e4];
    int4 d = ((const int4*)(ei + EE))[e4];
#pragma unroll
    for (int q = 0; q < 4; q++) {
        int src = (q == 0) ? s.x : (q == 1) ? s.y : (q == 2) ? s.z : s.w;
        int dst = (q == 0) ? d.x : (q == 1) ? d.y : (q == 2) ? d.z : d.w;
        int pos = atomicAdd(&g_cursor[dst], 1);
        if (pos < CAP) {
            g_col[dst * CAP + pos] = src;
        } else {
            int oi = atomicAdd(&g_overn, 1);
            if (oi < MAXOVER) g_over[oi] = make_int2(src, dst);
        }
    }
}

// ---------------------------------------------------------------------------
// 3: gather. One warp per node; lane owns a float2. 8-way edge unroll.
//    Overflow edges (normally none) folded in before the store.
// ---------------------------------------------------------------------------
__global__ void __launch_bounds__(256) k_gather(const float* __restrict__ x,
                                                const float* __restrict__ eps_p) {
    const int w = (blockIdx.x * blockDim.x + threadIdx.x) >> 5;
    const int lane = threadIdx.x & 31;
    if (w >= NN) return;
    const int beg = w * CAP;
    const int end = beg + min(g_cursor[w], CAP);
    const float2* __restrict__ x2 = (const float2*)x;   // row = 32 float2

    float s0x = 0.f, s0y = 0.f, s1x = 0.f, s1y = 0.f;
    float s2x = 0.f, s2y = 0.f, s3x = 0.f, s3y = 0.f;
    int j = beg;
    for (; j + 7 < end; j += 8) {
        int c0 = g_col[j],     c1 = g_col[j + 1];
        int c2 = g_col[j + 2], c3 = g_col[j + 3];
        int c4 = g_col[j + 4], c5 = g_col[j + 5];
        int c6 = g_col[j + 6], c7 = g_col[j + 7];
        float2 v0 = x2[(size_t)c0 * 32 + lane];
        float2 v1 = x2[(size_t)c1 * 32 + lane];
        float2 v2 = x2[(size_t)c2 * 32 + lane];
        float2 v3 = x2[(size_t)c3 * 32 + lane];
        float2 v4 = x2[(size_t)c4 * 32 + lane];
        float2 v5 = x2[(size_t)c5 * 32 + lane];
        float2 v6 = x2[(size_t)c6 * 32 + lane];
        float2 v7 = x2[(size_t)c7 * 32 + lane];
        s0x += v0.x; s0y += v0.y;  s1x += v1.x; s1y += v1.y;
        s2x += v2.x; s2y += v2.y;  s3x += v3.x; s3y += v3.y;
        s0x += v4.x; s0y += v4.y;  s1x += v5.x; s1y += v5.y;
        s2x += v6.x; s2y += v6.y;  s3x += v7.x; s3y += v7.y;
    }
    for (; j < end; j++) {
        int c0 = g_col[j];
        float2 v0 = x2[(size_t)c0 * 32 + lane];
        s0x += v0.x; s0y += v0.y;
    }
    const int novr = g_overn;
    if (novr > 0) {
        const int lim = novr < MAXOVER ? novr : MAXOVER;
        for (int e = 0; e < lim; e++) {
            int2 ed = g_over[e];
            if (ed.y == w) {
                float2 v = x2[(size_t)ed.x * 32 + lane];
                s0x += v.x; s0y += v.y;
            }
        }
    }
    const float sc = 1.f + *eps_p;
    float2 xv = x2[(size_t)w * 32 + lane];
    float2 o;
    o.x = sc * xv.x + ((s0x + s1x) + (s2x + s3x));
    o.y = sc * xv.y + ((s0y + s1y) + (s2y + s3y));
    ((float2*)g_h)[(size_t)w * 32 + lane] = o;
}

// ---------------------------------------------------------------------------
// 4: h1 = h @ W1 + b1 (FFMA2) with COALESCED smem staging in/out + fused
//    BN column stats. Global loads/stores are cooperative & coalesced;
//    per-row access happens in shared memory.
// ---------------------------------------------------------------------------
__global__ void __launch_bounds__(128) k_gemm1(const float* __restrict__ W1,
                                               const float* __restrict__ b1) {
    __shared__ __align__(16) float Ws[D * D];
    __shared__ __align__(16) float bs[D];
    __shared__ __align__(16) float st[128 * RPAD];   // 33.8 KB staging
    const int tid = threadIdx.x;
    const int row0 = blockIdx.x * 128;

    for (int i = tid; i < D * D; i += 128) Ws[i] = W1[i];
    if (tid < D) bs[tid] = b1[tid];

    // stage h: coalesced global -> smem (128 rows x 32 float2)
    const float2* __restrict__ h2 = (const float2*)g_h;
    for (int idx = tid; idx < 128 * 32; idx += 128) {
        int r = idx >> 5, c2 = idx & 31;
        int gr = row0 + r;
        float2 v = (gr < NN) ? h2[(size_t)gr * 32 + c2] : make_float2(0.f, 0.f);
        *(float2*)&st[r * RPAD + c2 * 2] = v;
    }
    __syncthreads();

    const bool valid = (row0 + tid) < NN;

    unsigned long long acc2[D / 2];
    const unsigned long long* bs2 = (const unsigned long long*)bs;
#pragma unroll
    for (int j = 0; j < D / 2; j++) acc2[j] = bs2[j];

    const float* hrow = &st[tid * RPAD];
    for (int k2 = 0; k2 < D / 2; k2++) {                // not unrolled: I$ safety
        float2 hv = *(const float2*)&hrow[k2 * 2];
#pragma unroll
        for (int kk = 0; kk < 2; kk++) {
            const float hk = (kk == 0) ? hv.x : hv.y;
            unsigned long long hk2;
            PACK_F32X2(hk2, hk, hk);
            const ulonglong2* wrow = (const ulonglong2*)&Ws[(k2 * 2 + kk) * D];
#pragma unroll
            for (int j8 = 0; j8 < D / 8; j8++) {
                ulonglong2 wv0 = wrow[j8 * 2];
                ulonglong2 wv1 = wrow[j8 * 2 + 1];
                FMA_F32X2(acc2[j8 * 4 + 0], hk2, wv0.x, acc2[j8 * 4 + 0]);
                FMA_F32X2(acc2[j8 * 4 + 1], hk2, wv0.y, acc2[j8 * 4 + 1]);
                FMA_F32X2(acc2[j8 * 4 + 2], hk2, wv1.x, acc2[j8 * 4 + 2]);
                FMA_F32X2(acc2[j8 * 4 + 3], hk2, wv1.y, acc2[j8 * 4 + 3]);
            }
        }
    }

    // overwrite OWN staged row with the result (no cross-thread hazard)
#pragma unroll
    for (int j = 0; j < D / 2; j++)
        *(unsigned long long*)&st[tid * RPAD + j * 2] = valid ? acc2[j] : 0ull;
    __syncthreads();

    // coalesced smem -> global store of h1
    float2* __restrict__ o2 = (float2*)g_h1;
    for (int idx = tid; idx < 128 * 32; idx += 128) {
        int r = idx >> 5, c2 = idx & 31;
        int gr = row0 + r;
        if (gr < NN)
            o2[(size_t)gr * 32 + c2] = *(const float2*)&st[r * RPAD + c2 * 2];
    }
    // fused BN stats from the staged outputs
    if (tid < D) {
        float s = 0.f, q = 0.f;
        for (int i = 0; i < 128; i++) {
            float v = st[i * RPAD + tid];
            s += v; q += v * v;
        }
        atomicAdd(&g_sum[tid], s);
        atomicAdd(&g_sumsq[tid], q);
    }
}

// ---------------------------------------------------------------------------
// 5: out = relu(BN(h1)) @ W2 + b2 — same coalesced staging structure.
// ---------------------------------------------------------------------------
__global__ void __launch_bounds__(128) k_gemm2(const float* __restrict__ W2,
                                               const float* __restrict__ b2,
                                               const float* __restrict__ gamma,
                                               const float* __restrict__ beta,
                                               float* __restrict__ out) {
    __shared__ __align__(16) float Ws[D * D];
    __shared__ __align__(16) float scl[D];
    __shared__ __align__(16) float sft[D];
    __shared__ __align__(16) float bs[D];
    __shared__ __align__(16) float st[128 * RPAD];
    const int tid = threadIdx.x;
    const int row0 = blockIdx.x * 128;

    for (int i = tid; i < D * D; i += 128) Ws[i] = W2[i];
    if (tid < D) {
        const float inv_n = 1.f / (float)NN;
        float mean = g_sum[tid] * inv_n;
        float var  = g_sumsq[tid] * inv_n - mean * mean;
        float rstd = rsqrtf(var + BN_EPS);
        float s = rstd * gamma[tid];
        scl[tid] = s;
        sft[tid] = beta[tid] - mean * s;
        bs[tid]  = b2[tid];
    }

    // stage h1: coalesced global -> smem
    const float2* __restrict__ h2 = (const float2*)g_h1;
    for (int idx = tid; idx < 128 * 32; idx += 128) {
        int r = idx >> 5, c2 = idx & 31;
        int gr = row0 + r;
        float2 v = (gr < NN) ? h2[(size_t)gr * 32 + c2] : make_float2(0.f, 0.f);
        *(float2*)&st[r * RPAD + c2 * 2] = v;
    }
    __syncthreads();

    unsigned long long acc2[D / 2];
    const unsigned long long* bs2 = (const unsigned long long*)bs;
#pragma unroll
    for (int j = 0; j < D / 2; j++) acc2[j] = bs2[j];

    const float* hrow = &st[tid * RPAD];
    for (int k2 = 0; k2 < D / 2; k2++) {
        float2 hv = *(const float2*)&hrow[k2 * 2];
#pragma unroll
        for (int kk = 0; kk < 2; kk++) {
            const int k = k2 * 2 + kk;
            float hk = (kk == 0) ? hv.x : hv.y;
            hk = fmaxf(hk * scl[k] + sft[k], 0.f);        // BN + ReLU
            unsigned long long hk2;
            PACK_F32X2(hk2, hk, hk);
            const ulonglong2* wrow = (const ulonglong2*)&Ws[k * D];
#pragma unroll
            for (int j8 = 0; j8 < D / 8; j8++) {
                ulonglong2 wv0 = wrow[j8 * 2];
                ulonglong2 wv1 = wrow[j8 * 2 + 1];
                FMA_F32X2(acc2[j8 * 4 + 0], hk2, wv0.x, acc2[j8 * 4 + 0]);
                FMA_F32X2(acc2[j8 * 4 + 1], hk2, wv0.y, acc2[j8 * 4 + 1]);
                FMA_F32X2(acc2[j8 * 4 + 2], hk2, wv1.x, acc2[j8 * 4 + 2]);
                FMA_F32X2(acc2[j8 * 4 + 3], hk2, wv1.y, acc2[j8 * 4 + 3]);
            }
        }
    }

#pragma unroll
    for (int j = 0; j < D / 2; j++)
        *(unsigned long long*)&st[tid * RPAD + j * 2] = acc2[j];
    __syncthreads();

    float2* __restrict__ o2 = (float2*)out;
    for (int idx = tid; idx < 128 * 32; idx += 128) {
        int r = idx >> 5, c2 = idx & 31;
        int gr = row0 + r;
        if (gr < NN)
            o2[(size_t)gr * 32 + c2] = *(const float2*)&st[r * RPAD + c2 * 2];
    }
}

// ---------------------------------------------------------------------------
extern "C" void kernel_launch(void* const* d_in, const int* in_sizes, int n_in,
                              void* d_out, int out_size) {
    const float* x     = (const float*)d_in[0];
    const int*   ei    = (const int*)  d_in[1];   // int32 (JAX demotes int64)
    const float* eps   = (const float*)d_in[2];
    const float* W1    = (const float*)d_in[3];
    const float* b1    = (const float*)d_in[4];
    const float* gamma = (const float*)d_in[5];
    const float* beta  = (const float*)d_in[6];
    const float* W2    = (const float*)d_in[7];
    const float* b2    = (const float*)d_in[8];
    float* out = (float*)d_out;

    k_zero  <<<(NN + 255) / 256, 256>>>();
    k_fill  <<<(EE / 4 + 255) / 256, 256>>>(ei);
    k_gather<<<(NN * 32 + 255) / 256, 256>>>(x, eps);
    k_gemm1 <<<(NN + 127) / 128, 128>>>(W1, b1);
    k_gemm2 <<<(NN + 127) / 128, 128>>>(W2, b2, gamma, beta, out);
}

// round 14
// speedup vs baseline: 1.2700x; 1.1387x over previous
#include <cuda_runtime.h>

#define NN 100000
#define EE 1600000
#define D 64
#define BN_EPS 1e-5f
#define CAP 64                       // per-node neighbor capacity (Poisson(16) max ~40)
#define MAXOVER 8192                 // overflow side-list capacity
#define RPAD 66                      // padded smem row stride (floats)

// Packed f32x2 FMA (Blackwell): d = a*b + c per 32-bit lane. PTX-only.
#define FMA_F32X2(d, a, b, c) \
    asm("fma.rn.f32x2 %0, %1, %2, %3;" : "=l"(d) : "l"(a), "l"(b), "l"(c))
#define PACK_F32X2(out, lo, hi) \
    asm("mov.b64 %0, {%1, %2};" : "=l"(out) : "f"(lo), "f"(hi))

// Scratch (device globals — no allocation allowed).
__device__ __align__(16) float g_h [NN * D];
__device__ __align__(16) float g_h1[NN * D];
__device__ __align__(16) float g_sum[D];
__device__ __align__(16) float g_sumsq[D];
__device__ __align__(16) int   g_cursor[NN];
__device__ __align__(16) int   g_col[NN * CAP];
__device__ __align__(16) int2  g_over[MAXOVER];
__device__            int      g_overn;

// ---------------------------------------------------------------------------
// 1: zero cursors + BN stat accumulators + overflow counter
// ---------------------------------------------------------------------------
__global__ void k_zero() {
    int i = blockIdx.x * blockDim.x + threadIdx.x;
    if (i < NN) g_cursor[i] = 0;
    if (i < D) { g_sum[i] = 0.f; g_sumsq[i] = 0.f; }
    if (i == D) g_overn = 0;
}

// ---------------------------------------------------------------------------
// 2: direct bucket scatter — no histogram, no scan.
// ---------------------------------------------------------------------------
__global__ void k_fill(const int* __restrict__ ei) {
    int e4 = blockIdx.x * blockDim.x + threadIdx.x;
    if (e4 >= EE / 4) return;
    int4 s = ((const int4*)ei)[e4];
    int4 d = ((const int4*)(ei + EE))[e4];
#pragma unroll
    for (int q = 0; q < 4; q++) {
        int src = (q == 0) ? s.x : (q == 1) ? s.y : (q == 2) ? s.z : s.w;
        int dst = (q == 0) ? d.x : (q == 1) ? d.y : (q == 2) ? d.z : d.w;
        int pos = atomicAdd(&g_cursor[dst], 1);
        if (pos < CAP) {
            g_col[dst * CAP + pos] = src;
        } else {
            int oi = atomicAdd(&g_overn, 1);
            if (oi < MAXOVER) g_over[oi] = make_int2(src, dst);
        }
    }
}

// ---------------------------------------------------------------------------
// 3: gather. One warp per node; lane owns a float2. 8-way edge unroll.
// ---------------------------------------------------------------------------
__global__ void __launch_bounds__(256) k_gather(const float* __restrict__ x,
                                                const float* __restrict__ eps_p) {
    const int w = (blockIdx.x * blockDim.x + threadIdx.x) >> 5;
    const int lane = threadIdx.x & 31;
    if (w >= NN) return;
    const int beg = w * CAP;
    const int end = beg + min(g_cursor[w], CAP);
    const float2* __restrict__ x2 = (const float2*)x;   // row = 32 float2

    float s0x = 0.f, s0y = 0.f, s1x = 0.f, s1y = 0.f;
    float s2x = 0.f, s2y = 0.f, s3x = 0.f, s3y = 0.f;
    int j = beg;
    for (; j + 7 < end; j += 8) {
        int c0 = g_col[j],     c1 = g_col[j + 1];
        int c2 = g_col[j + 2], c3 = g_col[j + 3];
        int c4 = g_col[j + 4], c5 = g_col[j + 5];
        int c6 = g_col[j + 6], c7 = g_col[j + 7];
        float2 v0 = x2[(size_t)c0 * 32 + lane];
        float2 v1 = x2[(size_t)c1 * 32 + lane];
        float2 v2 = x2[(size_t)c2 * 32 + lane];
        float2 v3 = x2[(size_t)c3 * 32 + lane];
        float2 v4 = x2[(size_t)c4 * 32 + lane];
        float2 v5 = x2[(size_t)c5 * 32 + lane];
        float2 v6 = x2[(size_t)c6 * 32 + lane];
        float2 v7 = x2[(size_t)c7 * 32 + lane];
        s0x += v0.x; s0y += v0.y;  s1x += v1.x; s1y += v1.y;
        s2x += v2.x; s2y += v2.y;  s3x += v3.x; s3y += v3.y;
        s0x += v4.x; s0y += v4.y;  s1x += v5.x; s1y += v5.y;
        s2x += v6.x; s2y += v6.y;  s3x += v7.x; s3y += v7.y;
    }
    for (; j < end; j++) {
        int c0 = g_col[j];
        float2 v0 = x2[(size_t)c0 * 32 + lane];
        s0x += v0.x; s0y += v0.y;
    }
    const int novr = g_overn;
    if (novr > 0) {
        const int lim = novr < MAXOVER ? novr : MAXOVER;
        for (int e = 0; e < lim; e++) {
            int2 ed = g_over[e];
            if (ed.y == w) {
                float2 v = x2[(size_t)ed.x * 32 + lane];
                s0x += v.x; s0y += v.y;
            }
        }
    }
    const float sc = 1.f + *eps_p;
    float2 xv = x2[(size_t)w * 32 + lane];
    float2 o;
    o.x = sc * xv.x + ((s0x + s1x) + (s2x + s3x));
    o.y = sc * xv.y + ((s0y + s1y) + (s2y + s3y));
    ((float2*)g_h)[(size_t)w * 32 + lane] = o;
}

// ---------------------------------------------------------------------------
// 4: h1 = h @ W1 + b1. 2-D register tiling: thread = 4 rows x 16 cols.
//    Coalesced smem staging in/out + fused BN column stats.
// ---------------------------------------------------------------------------
__global__ void __launch_bounds__(128) k_gemm1(const float* __restrict__ W1,
                                               const float* __restrict__ b1) {
    __shared__ __align__(16) float Ws[D * D];
    __shared__ __align__(16) float bs[D];
    __shared__ __align__(16) float st[128 * RPAD];
    const int tid = threadIdx.x;
    const int row0 = blockIdx.x * 128;

    for (int i = tid; i < D * D; i += 128) Ws[i] = W1[i];
    if (tid < D) bs[tid] = b1[tid];

    // stage h: coalesced global -> smem (128 rows x 32 float2)
    const float2* __restrict__ h2 = (const float2*)g_h;
    for (int idx = tid; idx < 128 * 32; idx += 128) {
        int r = idx >> 5, c2 = idx & 31;
        int gr = row0 + r;
        float2 v = (gr < NN) ? h2[(size_t)gr * 32 + c2] : make_float2(0.f, 0.f);
        *(float2*)&st[r * RPAD + c2 * 2] = v;
    }
    __syncthreads();

    const int rg = tid & 31;          // row within group; rows rg+32*r
    const int cg = tid >> 5;          // column group: cols [cg*16, cg*16+16)
    const float* hb = &st[rg * RPAD];

    unsigned long long acc[4][8];
    {
        const unsigned long long* bp = (const unsigned long long*)&bs[cg * 16];
#pragma unroll
        for (int j = 0; j < 8; j++) {
            unsigned long long b = bp[j];
            acc[0][j] = b; acc[1][j] = b; acc[2][j] = b; acc[3][j] = b;
        }
    }

    for (int k = 0; k < D; k++) {
        float h0 = hb[k];
        float h1v = hb[32 * RPAD + k];
        float h2v = hb[64 * RPAD + k];
        float h3v = hb[96 * RPAD + k];
        unsigned long long hp[4];
        PACK_F32X2(hp[0], h0, h0);
        PACK_F32X2(hp[1], h1v, h1v);
        PACK_F32X2(hp[2], h2v, h2v);
        PACK_F32X2(hp[3], h3v, h3v);
        const ulonglong2* wr = (const ulonglong2*)&Ws[k * D + cg * 16];
        ulonglong2 wv0 = wr[0], wv1 = wr[1], wv2 = wr[2], wv3 = wr[3];
        unsigned long long w[8] = { wv0.x, wv0.y, wv1.x, wv1.y,
                                    wv2.x, wv2.y, wv3.x, wv3.y };
#pragma unroll
        for (int r = 0; r < 4; r++)
#pragma unroll
            for (int j = 0; j < 8; j++)
                FMA_F32X2(acc[r][j], hp[r], w[j], acc[r][j]);
    }

    // all threads still read st as input until here
    __syncthreads();
#pragma unroll
    for (int r = 0; r < 4; r++) {
        int gr = row0 + rg + 32 * r;
        bool v = gr < NN;
        unsigned long long* dst =
            (unsigned long long*)&st[(rg + 32 * r) * RPAD + cg * 16];
#pragma unroll
        for (int j = 0; j < 8; j++) dst[j] = v ? acc[r][j] : 0ull;
    }
    __syncthreads();

    // coalesced smem -> global store of h1
    float2* __restrict__ o2 = (float2*)g_h1;
    for (int idx = tid; idx < 128 * 32; idx += 128) {
        int r = idx >> 5, c2 = idx & 31;
        int gr = row0 + r;
        if (gr < NN)
            o2[(size_t)gr * 32 + c2] = *(const float2*)&st[r * RPAD + c2 * 2];
    }
    // fused BN stats from the staged outputs (invalid rows are zeroed)
    if (tid < D) {
        float s = 0.f, q = 0.f;
        for (int i = 0; i < 128; i++) {
            float v = st[i * RPAD + tid];
            s += v; q += v * v;
        }
        atomicAdd(&g_sum[tid], s);
        atomicAdd(&g_sumsq[tid], q);
    }
}

// ---------------------------------------------------------------------------
// 5: out = relu(BN(h1)) @ W2 + b2. BN+ReLU applied during staging, then the
//    same 4x16 register-tiled GEMM.
// ---------------------------------------------------------------------------
__global__ void __launch_bounds__(128) k_gemm2(const float* __restrict__ W2,
                                               const float* __restrict__ b2,
                                               const float* __restrict__ gamma,
                                               const float* __restrict__ beta,
                                               float* __restrict__ out) {
    __shared__ __align__(16) float Ws[D * D];
    __shared__ __align__(16) float scl[D];
    __shared__ __align__(16) float sft[D];
    __shared__ __align__(16) float bs[D];
    __shared__ __align__(16) float st[128 * RPAD];
    const int tid = threadIdx.x;
    const int row0 = blockIdx.x * 128;

    for (int i = tid; i < D * D; i += 128) Ws[i] = W2[i];
    if (tid < D) {
        const float inv_n = 1.f / (float)NN;
        float mean = g_sum[tid] * inv_n;
        float var  = g_sumsq[tid] * inv_n - mean * mean;
        float rstd = rsqrtf(var + BN_EPS);
        float s = rstd * gamma[tid];
        scl[tid] = s;
        sft[tid] = beta[tid] - mean * s;
        bs[tid]  = b2[tid];
    }
    __syncthreads();                 // scl/sft needed by the staging transform

    // stage h1 with BN+ReLU applied elementwise (coalesced)
    const float2* __restrict__ h2 = (const float2*)g_h1;
    for (int idx = tid; idx < 128 * 32; idx += 128) {
        int r = idx >> 5, c2 = idx & 31;
        int gr = row0 + r;
        float2 v = (gr < NN) ? h2[(size_t)gr * 32 + c2] : make_float2(0.f, 0.f);
        float2 sc2 = *(const float2*)&scl[c2 * 2];
        float2 sf2 = *(const float2*)&sft[c2 * 2];
        v.x = fmaxf(v.x * sc2.x + sf2.x, 0.f);
        v.y = fmaxf(v.y * sc2.y + sf2.y, 0.f);
        *(float2*)&st[r * RPAD + c2 * 2] = v;
    }
    __syncthreads();

    const int rg = tid & 31;
    const int cg = tid >> 5;
    const float* hb = &st[rg * RPAD];

    unsigned long long acc[4][8];
    {
        const unsigned long long* bp = (const unsigned long long*)&bs[cg * 16];
#pragma unroll
        for (int j = 0; j < 8; j++) {
            unsigned long long b = bp[j];
            acc[0][j] = b; acc[1][j] = b; acc[2][j] = b; acc[3][j] = b;
        }
    }

    for (int k = 0; k < D; k++) {
        float h0 = hb[k];
        float h1v = hb[32 * RPAD + k];
        float h2v = hb[64 * RPAD + k];
        float h3v = hb[96 * RPAD + k];
        unsigned long long hp[4];
        PACK_F32X2(hp[0], h0, h0);
        PACK_F32X2(hp[1], h1v, h1v);
        PACK_F32X2(hp[2], h2v, h2v);
        PACK_F32X2(hp[3], h3v, h3v);
        const ulonglong2* wr = (const ulonglong2*)&Ws[k * D + cg * 16];
        ulonglong2 wv0 = wr[0], wv1 = wr[1], wv2 = wr[2], wv3 = wr[3];
        unsigned long long w[8] = { wv0.x, wv0.y, wv1.x, wv1.y,
                                    wv2.x, wv2.y, wv3.x, wv3.y };
#pragma unroll
        for (int r = 0; r < 4; r++)
#pragma unroll
            for (int j = 0; j < 8; j++)
                FMA_F32X2(acc[r][j], hp[r], w[j], acc[r][j]);
    }

    __syncthreads();
#pragma unroll
    for (int r = 0; r < 4; r++) {
        unsigned long long* dst =
            (unsigned long long*)&st[(rg + 32 * r) * RPAD + cg * 16];
#pragma unroll
        for (int j = 0; j < 8; j++) dst[j] = acc[r][j];
    }
    __syncthreads();

    float2* __restrict__ o2 = (float2*)out;
    for (int idx = tid; idx < 128 * 32; idx += 128) {
        int r = idx >> 5, c2 = idx & 31;
        int gr = row0 + r;
        if (gr < NN)
            o2[(size_t)gr * 32 + c2] = *(const float2*)&st[r * RPAD + c2 * 2];
    }
}

// ---------------------------------------------------------------------------
extern "C" void kernel_launch(void* const* d_in, const int* in_sizes, int n_in,
                              void* d_out, int out_size) {
    const float* x     = (const float*)d_in[0];
    const int*   ei    = (const int*)  d_in[1];   // int32 (JAX demotes int64)
    const float* eps   = (const float*)d_in[2];
    const float* W1    = (const float*)d_in[3];
    const float* b1    = (const float*)d_in[4];
    const float* gamma = (const float*)d_in[5];
    const float* beta  = (const float*)d_in[6];
    const float* W2    = (const float*)d_in[7];
    const float* b2    = (const float*)d_in[8];
    float* out = (float*)d_out;

    k_zero  <<<(NN + 255) / 256, 256>>>();
    k_fill  <<<(EE / 4 + 255) / 256, 256>>>(ei);
    k_gather<<<(NN * 32 + 255) / 256, 256>>>(x, eps);
    k_gemm1 <<<(NN + 127) / 128, 128>>>(W1, b1);
    k_gemm2 <<<(NN + 127) / 128, 128>>>(W2, b2, gamma, beta, out);
}

// round 15
// speedup vs baseline: 1.2819x; 1.0093x over previous
#include <cuda_runtime.h>

#define NN 100000
#define EE 1600000
#define D 64
#define BN_EPS 1e-5f
#define CAP 64                       // per-node neighbor capacity (Poisson(16) max ~40)
#define MAXOVER 8192                 // overflow side-list capacity
#define RPAD 66                      // padded smem row stride (floats)

// Packed f32x2 FMA (Blackwell): d = a*b + c per 32-bit lane. PTX-only.
#define FMA_F32X2(d, a, b, c) \
    asm("fma.rn.f32x2 %0, %1, %2, %3;" : "=l"(d) : "l"(a), "l"(b), "l"(c))
#define PACK_F32X2(out, lo, hi) \
    asm("mov.b64 %0, {%1, %2};" : "=l"(out) : "f"(lo), "f"(hi))

// Scratch (device globals — no allocation allowed).
__device__ __align__(16) float g_h [NN * D];
__device__ __align__(16) float g_h1[NN * D];
__device__ __align__(16) float g_sum[D];
__device__ __align__(16) float g_sumsq[D];
__device__ __align__(16) int   g_cursor[NN];
__device__ __align__(16) int   g_col[NN * CAP];
__device__ __align__(16) int2  g_over[MAXOVER];
__device__            int      g_overn;

// ---------------------------------------------------------------------------
// 1: zero cursors + BN stat accumulators + overflow counter
// ---------------------------------------------------------------------------
__global__ void k_zero() {
    int i = blockIdx.x * blockDim.x + threadIdx.x;
    if (i < NN) g_cursor[i] = 0;
    if (i < D) { g_sum[i] = 0.f; g_sumsq[i] = 0.f; }
    if (i == D) g_overn = 0;
}

// ---------------------------------------------------------------------------
// 2: direct bucket scatter — no histogram, no scan.
// ---------------------------------------------------------------------------
__global__ void k_fill(const int* __restrict__ ei) {
    int e4 = blockIdx.x * blockDim.x + threadIdx.x;
    if (e4 >= EE / 4) return;
    int4 s = ((const int4*)ei)[e4];
    int4 d = ((const int4*)(ei + EE))[e4];
#pragma unroll
    for (int q = 0; q < 4; q++) {
        int src = (q == 0) ? s.x : (q == 1) ? s.y : (q == 2) ? s.z : s.w;
        int dst = (q == 0) ? d.x : (q == 1) ? d.y : (q == 2) ? d.z : d.w;
        int pos = atomicAdd(&g_cursor[dst], 1);
        if (pos < CAP) {
            g_col[dst * CAP + pos] = src;
        } else {
            int oi = atomicAdd(&g_overn, 1);
            if (oi < MAXOVER) g_over[oi] = make_int2(src, dst);
        }
    }
}

// ---------------------------------------------------------------------------
// 3: gather. One warp per node; lane owns a float2. 8-way edge unroll.
// ---------------------------------------------------------------------------
__global__ void __launch_bounds__(256) k_gather(const float* __restrict__ x,
                                                const float* __restrict__ eps_p) {
    const int w = (blockIdx.x * blockDim.x + threadIdx.x) >> 5;
    const int lane = threadIdx.x & 31;
    if (w >= NN) return;
    const int beg = w * CAP;
    const int end = beg + min(g_cursor[w], CAP);
    const float2* __restrict__ x2 = (const float2*)x;   // row = 32 float2

    float s0x = 0.f, s0y = 0.f, s1x = 0.f, s1y = 0.f;
    float s2x = 0.f, s2y = 0.f, s3x = 0.f, s3y = 0.f;
    int j = beg;
    for (; j + 7 < end; j += 8) {
        int c0 = g_col[j],     c1 = g_col[j + 1];
        int c2 = g_col[j + 2], c3 = g_col[j + 3];
        int c4 = g_col[j + 4], c5 = g_col[j + 5];
        int c6 = g_col[j + 6], c7 = g_col[j + 7];
        float2 v0 = x2[(size_t)c0 * 32 + lane];
        float2 v1 = x2[(size_t)c1 * 32 + lane];
        float2 v2 = x2[(size_t)c2 * 32 + lane];
        float2 v3 = x2[(size_t)c3 * 32 + lane];
        float2 v4 = x2[(size_t)c4 * 32 + lane];
        float2 v5 = x2[(size_t)c5 * 32 + lane];
        float2 v6 = x2[(size_t)c6 * 32 + lane];
        float2 v7 = x2[(size_t)c7 * 32 + lane];
        s0x += v0.x; s0y += v0.y;  s1x += v1.x; s1y += v1.y;
        s2x += v2.x; s2y += v2.y;  s3x += v3.x; s3y += v3.y;
        s0x += v4.x; s0y += v4.y;  s1x += v5.x; s1y += v5.y;
        s2x += v6.x; s2y += v6.y;  s3x += v7.x; s3y += v7.y;
    }
    for (; j < end; j++) {
        int c0 = g_col[j];
        float2 v0 = x2[(size_t)c0 * 32 + lane];
        s0x += v0.x; s0y += v0.y;
    }
    const int novr = g_overn;
    if (novr > 0) {
        const int lim = novr < MAXOVER ? novr : MAXOVER;
        for (int e = 0; e < lim; e++) {
            int2 ed = g_over[e];
            if (ed.y == w) {
                float2 v = x2[(size_t)ed.x * 32 + lane];
                s0x += v.x; s0y += v.y;
            }
        }
    }
    const float sc = 1.f + *eps_p;
    float2 xv = x2[(size_t)w * 32 + lane];
    float2 o;
    o.x = sc * xv.x + ((s0x + s1x) + (s2x + s3x));
    o.y = sc * xv.y + ((s0y + s1y) + (s2y + s3y));
    ((float2*)g_h)[(size_t)w * 32 + lane] = o;
}

// ---------------------------------------------------------------------------
// Shared inner loop: 4 rows x 16 cols per thread, k-loop unrolled 2x with
// float2 h-loads; pragma unroll 2 gives ptxas a 4-k pipeline window.
// ---------------------------------------------------------------------------
__device__ __forceinline__ void gemm_tile_4x16(const float* __restrict__ hb,
                                               const float* __restrict__ Ws,
                                               int cg,
                                               unsigned long long acc[4][8]) {
#pragma unroll 2
    for (int k2 = 0; k2 < D / 2; k2++) {
        const int k = k2 * 2;
        float2 ha = *(const float2*)&hb[k];
        float2 hbv = *(const float2*)&hb[32 * RPAD + k];
        float2 hc = *(const float2*)&hb[64 * RPAD + k];
        float2 hd = *(const float2*)&hb[96 * RPAD + k];
        const ulonglong2* wr0 = (const ulonglong2*)&Ws[k * D + cg * 16];
        const ulonglong2* wr1 = (const ulonglong2*)&Ws[(k + 1) * D + cg * 16];
        ulonglong2 a0 = wr0[0], a1 = wr0[1], a2 = wr0[2], a3 = wr0[3];
        ulonglong2 b0 = wr1[0], b1 = wr1[1], b2 = wr1[2], b3 = wr1[3];
        unsigned long long w0[8] = { a0.x, a0.y, a1.x, a1.y, a2.x, a2.y, a3.x, a3.y };
        unsigned long long w1[8] = { b0.x, b0.y, b1.x, b1.y, b2.x, b2.y, b3.x, b3.y };
        unsigned long long hp0[4], hp1[4];
        PACK_F32X2(hp0[0], ha.x, ha.x);   PACK_F32X2(hp1[0], ha.y, ha.y);
        PACK_F32X2(hp0[1], hbv.x, hbv.x); PACK_F32X2(hp1[1], hbv.y, hbv.y);
        PACK_F32X2(hp0[2], hc.x, hc.x);   PACK_F32X2(hp1[2], hc.y, hc.y);
        PACK_F32X2(hp0[3], hd.x, hd.x);   PACK_F32X2(hp1[3], hd.y, hd.y);
#pragma unroll
        for (int r = 0; r < 4; r++)
#pragma unroll
            for (int j = 0; j < 8; j++)
                FMA_F32X2(acc[r][j], hp0[r], w0[j], acc[r][j]);
#pragma unroll
        for (int r = 0; r < 4; r++)
#pragma unroll
            for (int j = 0; j < 8; j++)
                FMA_F32X2(acc[r][j], hp1[r], w1[j], acc[r][j]);
    }
}

// ---------------------------------------------------------------------------
// 4: h1 = h @ W1 + b1. 4x16 register tile, pipelined k-loop, coalesced
//    staging in/out + fused BN column stats.
// ---------------------------------------------------------------------------
__global__ void __launch_bounds__(128, 4) k_gemm1(const float* __restrict__ W1,
                                                  const float* __restrict__ b1) {
    __shared__ __align__(16) float Ws[D * D];
    __shared__ __align__(16) float bs[D];
    __shared__ __align__(16) float st[128 * RPAD];
    const int tid = threadIdx.x;
    const int row0 = blockIdx.x * 128;

    for (int i = tid; i < D * D; i += 128) Ws[i] = W1[i];
    if (tid < D) bs[tid] = b1[tid];

    const float2* __restrict__ h2 = (const float2*)g_h;
    for (int idx = tid; idx < 128 * 32; idx += 128) {
        int r = idx >> 5, c2 = idx & 31;
        int gr = row0 + r;
        float2 v = (gr < NN) ? h2[(size_t)gr * 32 + c2] : make_float2(0.f, 0.f);
        *(float2*)&st[r * RPAD + c2 * 2] = v;
    }
    __syncthreads();

    const int rg = tid & 31;
    const int cg = tid >> 5;
    const float* hb = &st[rg * RPAD];

    unsigned long long acc[4][8];
    {
        const unsigned long long* bp = (const unsigned long long*)&bs[cg * 16];
#pragma unroll
        for (int j = 0; j < 8; j++) {
            unsigned long long b = bp[j];
            acc[0][j] = b; acc[1][j] = b; acc[2][j] = b; acc[3][j] = b;
        }
    }

    gemm_tile_4x16(hb, Ws, cg, acc);

    __syncthreads();
#pragma unroll
    for (int r = 0; r < 4; r++) {
        int gr = row0 + rg + 32 * r;
        bool v = gr < NN;
        unsigned long long* dst =
            (unsigned long long*)&st[(rg + 32 * r) * RPAD + cg * 16];
#pragma unroll
        for (int j = 0; j < 8; j++) dst[j] = v ? acc[r][j] : 0ull;
    }
    __syncthreads();

    float2* __restrict__ o2 = (float2*)g_h1;
    for (int idx = tid; idx < 128 * 32; idx += 128) {
        int r = idx >> 5, c2 = idx & 31;
        int gr = row0 + r;
        if (gr < NN)
            o2[(size_t)gr * 32 + c2] = *(const float2*)&st[r * RPAD + c2 * 2];
    }
    if (tid < D) {
        float s = 0.f, q = 0.f;
        for (int i = 0; i < 128; i++) {
            float v = st[i * RPAD + tid];
            s += v; q += v * v;
        }
        atomicAdd(&g_sum[tid], s);
        atomicAdd(&g_sumsq[tid], q);
    }
}

// ---------------------------------------------------------------------------
// 5: out = relu(BN(h1)) @ W2 + b2. BN+ReLU during staging, same tiled GEMM.
// ---------------------------------------------------------------------------
__global__ void __launch_bounds__(128, 4) k_gemm2(const float* __restrict__ W2,
                                                  const float* __restrict__ b2,
                                                  const float* __restrict__ gamma,
                                                  const float* __restrict__ beta,
                                                  float* __restrict__ out) {
    __shared__ __align__(16) float Ws[D * D];
    __shared__ __align__(16) float scl[D];
    __shared__ __align__(16) float sft[D];
    __shared__ __align__(16) float bs[D];
    __shared__ __align__(16) float st[128 * RPAD];
    const int tid = threadIdx.x;
    const int row0 = blockIdx.x * 128;

    for (int i = tid; i < D * D; i += 128) Ws[i] = W2[i];
    if (tid < D) {
        const float inv_n = 1.f / (float)NN;
        float mean = g_sum[tid] * inv_n;
        float var  = g_sumsq[tid] * inv_n - mean * mean;
        float rstd = rsqrtf(var + BN_EPS);
        float s = rstd * gamma[tid];
        scl[tid] = s;
        sft[tid] = beta[tid] - mean * s;
        bs[tid]  = b2[tid];
    }
    __syncthreads();

    const float2* __restrict__ h2 = (const float2*)g_h1;
    for (int idx = tid; idx < 128 * 32; idx += 128) {
        int r = idx >> 5, c2 = idx & 31;
        int gr = row0 + r;
        float2 v = (gr < NN) ? h2[(size_t)gr * 32 + c2] : make_float2(0.f, 0.f);
        float2 sc2 = *(const float2*)&scl[c2 * 2];
        float2 sf2 = *(const float2*)&sft[c2 * 2];
        v.x = fmaxf(v.x * sc2.x + sf2.x, 0.f);
        v.y = fmaxf(v.y * sc2.y + sf2.y, 0.f);
        *(float2*)&st[r * RPAD + c2 * 2] = v;
    }
    __syncthreads();

    const int rg = tid & 31;
    const int cg = tid >> 5;
    const float* hb = &st[rg * RPAD];

    unsigned long long acc[4][8];
    {
        const unsigned long long* bp = (const unsigned long long*)&bs[cg * 16];
#pragma unroll
        for (int j = 0; j < 8; j++) {
            unsigned long long b = bp[j];
            acc[0][j] = b; acc[1][j] = b; acc[2][j] = b; acc[3][j] = b;
        }
    }

    gemm_tile_4x16(hb, Ws, cg, acc);

    __syncthreads();
#pragma unroll
    for (int r = 0; r < 4; r++) {
        unsigned long long* dst =
            (unsigned long long*)&st[(rg + 32 * r) * RPAD + cg * 16];
#pragma unroll
        for (int j = 0; j < 8; j++) dst[j] = acc[r][j];
    }
    __syncthreads();

    float2* __restrict__ o2 = (float2*)out;
    for (int idx = tid; idx < 128 * 32; idx += 128) {
        int r = idx >> 5, c2 = idx & 31;
        int gr = row0 + r;
        if (gr < NN)
            o2[(size_t)gr * 32 + c2] = *(const float2*)&st[r * RPAD + c2 * 2];
    }
}

// ---------------------------------------------------------------------------
extern "C" void kernel_launch(void* const* d_in, const int* in_sizes, int n_in,
                              void* d_out, int out_size) {
    const float* x     = (const float*)d_in[0];
    const int*   ei    = (const int*)  d_in[1];   // int32 (JAX demotes int64)
    const float* eps   = (const float*)d_in[2];
    const float* W1    = (const float*)d_in[3];
    const float* b1    = (const float*)d_in[4];
    const float* gamma = (const float*)d_in[5];
    const float* beta  = (const float*)d_in[6];
    const float* W2    = (const float*)d_in[7];
    const float* b2    = (const float*)d_in[8];
    float* out = (float*)d_out;

    k_zero  <<<(NN + 255) / 256, 256>>>();
    k_fill  <<<(EE / 4 + 255) / 256, 256>>>(ei);
    k_gather<<<(NN * 32 + 255) / 256, 256>>>(x, eps);
    k_gemm1 <<<(NN + 127) / 128, 128>>>(W1, b1);
    k_gemm2 <<<(NN + 127) / 128, 128>>>(W2, b2, gamma, beta, out);
}